// round 17
// baseline (speedup 1.0000x reference)
#include <cuda_runtime.h>
#include <cuda_bf16.h>
#include <cuda_fp16.h>
#include <math.h>

#define D 128
#define H 4
#define DK 32
#define BATCH 16
#define SEQ 2048
#define ROWS (BATCH*SEQ)   // 32768
#define LNEPS 1e-5f

// ---------------- scratch (static device globals; no allocs allowed) ----------
__device__ float g_xn[ROWS*D];
__device__ float g_sa[ROWS*D];
__device__ __half g_wh[5*D*D];            // fp16 weights (q,k,v,w1,w2)
__device__ int   g_cnt[BATCH];
__device__ int   g_idx[BATCH*SEQ];
__device__ __half g_qh[ROWS*D];           // fp16 Q (relu'd)
__device__ __half g_kh[ROWS*D];           // fp16 K
__device__ __half g_vh[ROWS*D];           // fp16 V

// ---------------- helpers ------------------------------------------------------
__device__ __forceinline__ unsigned packh(float a, float b) {
    __half2 t = __floats2half2_rn(a, b);
    return *(unsigned*)&t;
}
__device__ __forceinline__ unsigned h2exp2(float a, float b) {
    unsigned u = packh(a, b), r;
    asm("ex2.approx.f16x2 %0, %1;" : "=r"(r) : "r"(u));
    return r;
}

#define MMA_F16(c, a, b0, b1) \
    asm volatile("mma.sync.aligned.m16n8k16.row.col.f32.f16.f16.f32 " \
        "{%0,%1,%2,%3}, {%4,%5,%6,%7}, {%8,%9}, {%0,%1,%2,%3};" \
        : "+f"(c[0]), "+f"(c[1]), "+f"(c[2]), "+f"(c[3]) \
        : "r"(a[0]), "r"(a[1]), "r"(a[2]), "r"(a[3]), "r"(b0), "r"(b1))

#define LDSM_X4(r, addr) \
    asm volatile("ldmatrix.sync.aligned.m8n8.x4.shared.b16 {%0,%1,%2,%3}, [%4];" \
        : "=r"(r[0]), "=r"(r[1]), "=r"(r[2]), "=r"(r[3]) : "r"(addr))

#define LDSM_X4_T(r, addr) \
    asm volatile("ldmatrix.sync.aligned.m8n8.x4.trans.shared.b16 {%0,%1,%2,%3}, [%4];" \
        : "=r"(r[0]), "=r"(r[1]), "=r"(r[2]), "=r"(r[3]) : "r"(addr))

#define CPA16(dst, src, pbytes) \
    asm volatile("cp.async.cg.shared.global [%0], [%1], 16, %2;" \
        :: "r"(dst), "l"(src), "r"(pbytes))
#define CPC() asm volatile("cp.async.commit_group;" ::: "memory")
#define CPW0() asm volatile("cp.async.wait_group 0;" ::: "memory")
#define CPW1() asm volatile("cp.async.wait_group 1;" ::: "memory")

__device__ __forceinline__ unsigned s2u(const void* p) {
    return (unsigned)__cvta_generic_to_shared(p);
}

#define AH 136     // fp16 A-tile stride (halves)
#define WH 72      // fp16 W-chunk stride (halves): 144B rows, conflict-free LDSM
#define MT 64      // GEMM M-tile rows
#define GEMM_SMEM (MT*AH*2 + 2*128*WH*2)    // 54272 B -> 4 CTA/SM

// ---- LayerNorm rows straight from gmem -> fp16 smem tile (+ optional fp32 out)
__device__ __forceinline__ void ln_gmem_f16(const float* __restrict__ X, int rowBase,
        int tid, const float* __restrict__ w, const float* __restrict__ b,
        __half* sAh, float* __restrict__ xn_out) {
    int hw = tid >> 4;          // half-warp id 0..15
    int l  = tid & 15;
    float4 w0 = ((const float4*)w)[l*2], w1 = ((const float4*)w)[l*2+1];
    float4 b0 = ((const float4*)b)[l*2], b1 = ((const float4*)b)[l*2+1];
    #pragma unroll
    for (int it = 0; it < MT/16; it++) {
        int row = it * 16 + hw;
        const float4* xp = (const float4*)(X + (size_t)(rowBase + row) * D + l * 8);
        float4 v0 = xp[0], v1 = xp[1];
        float s = v0.x+v0.y+v0.z+v0.w + v1.x+v1.y+v1.z+v1.w;
        #pragma unroll
        for (int o = 8; o; o >>= 1) s += __shfl_xor_sync(0xffffffffu, s, o);
        float mu = s * (1.0f / D);
        float d0x=v0.x-mu, d0y=v0.y-mu, d0z=v0.z-mu, d0w=v0.w-mu;
        float d1x=v1.x-mu, d1y=v1.y-mu, d1z=v1.z-mu, d1w=v1.w-mu;
        float ss = d0x*d0x+d0y*d0y+d0z*d0z+d0w*d0w + d1x*d1x+d1y*d1y+d1z*d1z+d1w*d1w;
        #pragma unroll
        for (int o = 8; o; o >>= 1) ss += __shfl_xor_sync(0xffffffffu, ss, o);
        float rstd = rsqrtf(ss * (1.0f / D) + LNEPS);
        float o0x = d0x*rstd*w0.x + b0.x, o0y = d0y*rstd*w0.y + b0.y;
        float o0z = d0z*rstd*w0.z + b0.z, o0w = d0w*rstd*w0.w + b0.w;
        float o1x = d1x*rstd*w1.x + b1.x, o1y = d1y*rstd*w1.y + b1.y;
        float o1z = d1z*rstd*w1.z + b1.z, o1w = d1w*rstd*w1.w + b1.w;
        uint4 u;
        u.x = packh(o0x, o0y); u.y = packh(o0z, o0w);
        u.z = packh(o1x, o1y); u.w = packh(o1z, o1w);
        *(uint4*)&sAh[row * AH + l * 8] = u;
        if (xn_out) {
            float4* op = (float4*)(xn_out + (size_t)(rowBase + row) * D + l * 8);
            op[0] = make_float4(o0x, o0y, o0z, o0w);
            op[1] = make_float4(o1x, o1y, o1z, o1w);
        }
    }
}

// ---------------- prep: mask compaction + fp16-convert all weights -------------
__global__ void prep_kernel(const int* __restrict__ mask,
                            int* __restrict__ idx, int* __restrict__ cnt,
                            const float* __restrict__ wq, const float* __restrict__ wk,
                            const float* __restrict__ wv, const float* __restrict__ w1,
                            const float* __restrict__ w2, __half* __restrict__ wh) {
    __shared__ int wsum[32];
    if (blockIdx.x >= 16) {
        int i = (blockIdx.x - 16) * 1024 + threadIdx.x;
        int which = i >> 14, off = i & 16383;
        const float* srcs[5] = {wq, wk, wv, w1, w2};
        wh[i] = __float2half(srcs[which][off]);
        return;
    }
    int b = blockIdx.x, t = threadIdx.x;
    const int* mb = mask + b * SEQ;
    int m0 = mb[2*t], m1 = mb[2*t+1];
    int s = m0 + m1;
    int lane = t & 31, w = t >> 5;
    int v = s;
    #pragma unroll
    for (int o = 1; o < 32; o <<= 1) {
        int u = __shfl_up_sync(0xffffffffu, v, o);
        if (lane >= o) v += u;
    }
    if (lane == 31) wsum[w] = v;
    __syncthreads();
    if (t < 32) {
        int u = wsum[t];
        #pragma unroll
        for (int o = 1; o < 32; o <<= 1) {
            int x = __shfl_up_sync(0xffffffffu, u, o);
            if (t >= o) u += x;
        }
        wsum[t] = u;
    }
    __syncthreads();
    int p = v - s + (w ? wsum[w-1] : 0);
    if (m0) idx[b*SEQ + p++] = 2*t;
    if (m1) idx[b*SEQ + p]   = 2*t + 1;
    if (t == 1023) cnt[b] = wsum[31];
}

// ---- W chunk streamer: 128 rows x 64 fp16 cols of weight, K-chunk kc ----------
__device__ __forceinline__ void stream_wchunk(__half* dst, const __half* __restrict__ W,
                                              int kc, int tid) {
    #pragma unroll
    for (int j = 0; j < 4; j++) {
        int i = tid + j * 256;
        int n = i >> 3, seg = (i & 7) * 8;     // 8 halves = 16B
        CPA16(s2u(dst + n * WH + seg), &W[(size_t)n * D + kc * 64 + seg], 16);
    }
}

// -------- QKV GEMM (fp16, M=64 tiles, K=64 chunks): fused LN -------------------
__global__ __launch_bounds__(256, 4) void qkv_kernel(const float* __restrict__ X,
        const __half* __restrict__ W0, const __half* __restrict__ W1,
        const __half* __restrict__ W2,
        const float* __restrict__ lnw, const float* __restrict__ lnb,
        float* __restrict__ xn_out,
        __half* __restrict__ O0, __half* __restrict__ O1, __half* __restrict__ O2) {
    extern __shared__ __half smh[];
    __half* sA  = smh;                    // MT x AH
    __half* sW0 = smh + MT * AH;          // 128 x WH
    __half* sW1 = sW0 + 128 * WH;
    int tid = threadIdx.x, warp = tid >> 5, lane = tid & 31;
    int rq = warp >> 1, nh = warp & 1;
    int g = lane >> 2, tig = lane & 3;
    int rowBase = blockIdx.x * MT;

    const __half* Ws[3] = {W0, W1, W2};
    __half* Os[3] = {O0, O1, O2};

    stream_wchunk(sW0, W0, 0, tid);
    CPC();
    ln_gmem_f16(X, rowBase, tid, lnw, lnb, sA, xn_out);
    CPW0();
    __syncthreads();

    unsigned aBase = s2u(sA) +
        (((rq * 16 + (lane & 7) + ((lane >> 3) & 1) * 8) * AH + (lane >> 4) * 8) << 1);
    unsigned wOff = ((((lane & 7) + nh * 64) * WH + (lane >> 3) * 8) << 1);
    unsigned wBase[2] = { s2u(sW0) + wOff, s2u(sW1) + wOff };

    float c[8][4] = {};
    int buf = 0;

    #pragma unroll
    for (int t = 0; t < 6; t++) {
        int wi = t >> 1, kc = t & 1;
        if (t) __syncthreads();
        if (t + 1 < 6) {
            stream_wchunk(buf ? sW0 : sW1, Ws[(t + 1) >> 1], (t + 1) & 1, tid);
            CPC();
            CPW1();
        } else {
            CPW0();
        }
        __syncthreads();

        unsigned a[4][4];
        #pragma unroll
        for (int ks = 0; ks < 4; ks++)
            LDSM_X4(a[ks], aBase + kc * 128 + ks * 32);
        #pragma unroll
        for (int nt = 0; nt < 8; nt++) {
            unsigned wb0[4], wb1[4];
            LDSM_X4(wb0, wBase[buf] + nt * (8 * WH * 2));
            LDSM_X4(wb1, wBase[buf] + nt * (8 * WH * 2) + 64);
            MMA_F16(c[nt], a[0], wb0[0], wb0[1]);
            MMA_F16(c[nt], a[1], wb0[2], wb0[3]);
            MMA_F16(c[nt], a[2], wb1[0], wb1[1]);
            MMA_F16(c[nt], a[3], wb1[2], wb1[3]);
        }

        if (kc == 1) {
            __half* O = Os[wi];
            int row0 = rowBase + rq * 16 + g;
            bool relu = (wi == 0);
            #pragma unroll
            for (int nt = 0; nt < 8; nt++) {
                int col = nh * 64 + nt * 8 + 2 * tig;
                float lx = c[nt][0], ly = c[nt][1], hx = c[nt][2], hy = c[nt][3];
                if (relu) {
                    lx = fmaxf(lx, 0.f); ly = fmaxf(ly, 0.f);
                    hx = fmaxf(hx, 0.f); hy = fmaxf(hy, 0.f);
                }
                *(unsigned*)&O[(size_t)row0 * D + col]       = packh(lx, ly);
                *(unsigned*)&O[(size_t)(row0 + 8) * D + col] = packh(hx, hy);
                c[nt][0] = 0.f; c[nt][1] = 0.f; c[nt][2] = 0.f; c[nt][3] = 0.f;
            }
        }
        buf ^= 1;
    }
}

// -------- FFN (fp16, M=64, K=64 chunks): out = sa + relu(LN(sa)@w1+b1)@w2 + b2 -
__global__ __launch_bounds__(256, 4) void ffn_kernel(const float* __restrict__ SA,
        const __half* __restrict__ W1, const __half* __restrict__ W2,
        const float* __restrict__ lnw, const float* __restrict__ lnb,
        const float* __restrict__ b1v, const float* __restrict__ b2v,
        float* __restrict__ out) {
    extern __shared__ __half smh[];
    __half* sA  = smh;
    __half* sW0 = smh + MT * AH;
    __half* sW1 = sW0 + 128 * WH;
    int tid = threadIdx.x, warp = tid >> 5, lane = tid & 31;
    int rq = warp >> 1, nh = warp & 1;
    int g = lane >> 2, tig = lane & 3;
    int rowBase = blockIdx.x * MT;

    stream_wchunk(sW0, W1, 0, tid);
    CPC();
    ln_gmem_f16(SA, rowBase, tid, lnw, lnb, sA, nullptr);
    CPW0();
    __syncthreads();

    unsigned aBase = s2u(sA) +
        (((rq * 16 + (lane & 7) + ((lane >> 3) & 1) * 8) * AH + (lane >> 4) * 8) << 1);
    unsigned wOff = ((((lane & 7) + nh * 64) * WH + (lane >> 3) * 8) << 1);
    unsigned wBase[2] = { s2u(sW0) + wOff, s2u(sW1) + wOff };

    float c[8][4] = {};
    int buf = 0;

    #pragma unroll
    for (int t = 0; t < 4; t++) {
        int kc = t & 1;
        if (t) __syncthreads();
        if (t + 1 < 4) {
            stream_wchunk(buf ? sW0 : sW1, (t + 1 < 2) ? W1 : W2, (t + 1) & 1, tid);
            CPC();
            CPW1();
        } else {
            CPW0();
        }
        __syncthreads();

        unsigned a[4][4];
        #pragma unroll
        for (int ks = 0; ks < 4; ks++)
            LDSM_X4(a[ks], aBase + kc * 128 + ks * 32);
        #pragma unroll
        for (int nt = 0; nt < 8; nt++) {
            unsigned wb0[4], wb1[4];
            LDSM_X4(wb0, wBase[buf] + nt * (8 * WH * 2));
            LDSM_X4(wb1, wBase[buf] + nt * (8 * WH * 2) + 64);
            MMA_F16(c[nt], a[0], wb0[0], wb0[1]);
            MMA_F16(c[nt], a[1], wb0[2], wb0[3]);
            MMA_F16(c[nt], a[2], wb1[0], wb1[1]);
            MMA_F16(c[nt], a[3], wb1[2], wb1[3]);
        }

        if (t == 1) {
            __syncthreads();
            int row0l = rq * 16 + g;
            #pragma unroll
            for (int nt = 0; nt < 8; nt++) {
                int col = nh * 64 + nt * 8 + 2 * tig;
                float2 bb = *(const float2*)&b1v[col];
                *(unsigned*)&sA[row0l * AH + col] =
                    packh(fmaxf(c[nt][0] + bb.x, 0.f), fmaxf(c[nt][1] + bb.y, 0.f));
                *(unsigned*)&sA[(row0l + 8) * AH + col] =
                    packh(fmaxf(c[nt][2] + bb.x, 0.f), fmaxf(c[nt][3] + bb.y, 0.f));
                c[nt][0] = 0.f; c[nt][1] = 0.f; c[nt][2] = 0.f; c[nt][3] = 0.f;
            }
        }
        if (t == 3) {
            int row0 = rowBase + rq * 16 + g;
            #pragma unroll
            for (int nt = 0; nt < 8; nt++) {
                int col = nh * 64 + nt * 8 + 2 * tig;
                float2 bb = *(const float2*)&b2v[col];
                float2 r0v = *(const float2*)&SA[(size_t)row0 * D + col];
                float2 r1v = *(const float2*)&SA[(size_t)(row0 + 8) * D + col];
                float2 lo = make_float2(c[nt][0] + bb.x + r0v.x, c[nt][1] + bb.y + r0v.y);
                float2 hi = make_float2(c[nt][2] + bb.x + r1v.x, c[nt][3] + bb.y + r1v.y);
                *(float2*)&out[(size_t)row0 * D + col] = lo;
                *(float2*)&out[(size_t)(row0 + 8) * D + col] = hi;
            }
        }
        buf ^= 1;
    }
}

// ---------------- fp16 flash attention: 128-key tiles, two halves per sync -----
// One CPW0 + prefetch + 2 syncthreads per 128 keys (halved vs 64-key tiles).
// The two 64-key halves are processed sequentially (#pragma unroll 1) reusing
// the same p-registers, preserving the ~64-reg / 4 CTA-per-SM profile.
#define AKS 40
__global__ __launch_bounds__(256, 4) void attn_f16_kernel(
        const __half* __restrict__ gqh, const __half* __restrict__ gkh,
        const __half* __restrict__ gvh, const int* __restrict__ idx,
        const int* __restrict__ cnt, const float* __restrict__ xn,
        float* __restrict__ sa) {
    __shared__ __half sK[2][2][64][AKS];
    __shared__ __half sV[2][2][64][AKS];

    int tid = threadIdx.x;
    int warp = tid >> 5, lane = tid & 31;
    int g = lane >> 2, tig = lane & 3;
    int b = blockIdx.y >> 2, h = blockIdx.y & 3;
    int q0 = blockIdx.x * 128 + warp * 16;
    int nb = cnt[b];
    const int* bidx = idx + b * SEQ;

    unsigned onesb = (lane < 4) ? 0x3C003C00u : 0u;

    const float qs = 0.17677669529663687f * 1.4426950408889634f;
    const __half* qp0 = gqh + (size_t)(b * SEQ + q0 + g) * D + h * DK;
    const __half* qp1 = qp0 + 8 * D;
    unsigned qa[2][4];
    #pragma unroll
    for (int ks = 0; ks < 2; ks++) {
        int base = ks * 16 + 2 * tig;
        qa[ks][0] = packh(__half2float(qp0[base]) * qs,     __half2float(qp0[base + 1]) * qs);
        qa[ks][1] = packh(__half2float(qp1[base]) * qs,     __half2float(qp1[base + 1]) * qs);
        qa[ks][2] = packh(__half2float(qp0[base + 8]) * qs, __half2float(qp0[base + 9]) * qs);
        qa[ks][3] = packh(__half2float(qp1[base + 8]) * qs, __half2float(qp1[base + 9]) * qs);
    }

    float o[5][4] = {};          // [0..3]: O d-tiles; [4]: l tile (col 0)

    int fKey = tid >> 2, fSeg = (tid & 3) * 8;
    size_t headOff = (size_t)b * SEQ * D + h * DK + fSeg;

    int kRow = lane & 7, kCol = (lane >> 3) * 8;
    int vKey = ((lane >> 3) & 1) * 8 + (lane & 7);
    int vCol = (lane >> 4) * 8;

    // prologue: fill 128-key tile 0 (both halves) into buffer 0
    {
        #pragma unroll
        for (int hf = 0; hf < 2; hf++) {
            int key = hf * 64 + fKey;
            int p = (key < nb) ? 16 : 0;
            int gi = (key < nb) ? bidx[key] : 0;
            CPA16(s2u(&sK[0][hf][fKey][fSeg]), gkh + headOff + (size_t)gi * D, p);
            CPA16(s2u(&sV[0][hf][fKey][fSeg]), gvh + headOff + (size_t)gi * D, p);
        }
        CPC();
    }

    int buf = 0;
    for (int kb = 0; kb < nb; kb += 128, buf ^= 1) {
        CPW0();
        __syncthreads();
        if (kb + 128 < nb) {
            #pragma unroll
            for (int hf = 0; hf < 2; hf++) {
                int key = kb + 128 + hf * 64 + fKey;
                int p = (key < nb) ? 16 : 0;
                int gi = (key < nb) ? bidx[key] : 0;
                CPA16(s2u(&sK[buf ^ 1][hf][fKey][fSeg]), gkh + headOff + (size_t)gi * D, p);
                CPA16(s2u(&sV[buf ^ 1][hf][fKey][fSeg]), gvh + headOff + (size_t)gi * D, p);
            }
            CPC();
        }

        #pragma unroll 1
        for (int hf = 0; hf < 2; hf++) {
            int base = kb + hf * 64;
            if (base >= nb) break;              // nb uniform across block
            int kv = min(64, nb - base);
            unsigned kAddr = s2u(&sK[buf][hf][kRow][kCol]);
            unsigned vAddr = s2u(&sV[buf][hf][vKey][vCol]);

            // S = Q K^T with exp fused per n-tile
            unsigned p01[8], p23[8];
            #pragma unroll
            for (int nt = 0; nt < 8; nt++) {
                float s4[4] = {0.f, 0.f, 0.f, 0.f};
                unsigned kf[4];
                LDSM_X4(kf, kAddr + nt * 8 * AKS * 2);
                MMA_F16(s4, qa[0], kf[0], kf[1]);
                MMA_F16(s4, qa[1], kf[2], kf[3]);
                if (kv < 64) {
                    int col = nt * 8 + 2 * tig;
                    if (col     >= kv) { s4[0] = -1000.f; s4[2] = -1000.f; }
                    if (col + 1 >= kv) { s4[1] = -1000.f; s4[3] = -1000.f; }
                }
                p01[nt] = h2exp2(s4[0], s4[1]);
                p23[nt] = h2exp2(s4[2], s4[3]);
            }

            // O += P V ; l += P 1
            #pragma unroll
            for (int ksp = 0; ksp < 4; ksp++) {
                unsigned pa[4] = { p01[2*ksp], p23[2*ksp], p01[2*ksp+1], p23[2*ksp+1] };
                #pragma unroll
                for (int dh = 0; dh < 2; dh++) {
                    unsigned vb[4];
                    LDSM_X4_T(vb, vAddr + (ksp * 16 * AKS + dh * 16) * 2);
                    MMA_F16(o[dh*2 + 0], pa, vb[0], vb[1]);
                    MMA_F16(o[dh*2 + 1], pa, vb[2], vb[3]);
                }
                MMA_F16(o[4], pa, onesb, onesb);
            }
        }
    }

    // epilogue: sa = xn + O/l
    float l0 = __shfl_sync(0xffffffffu, o[4][0], lane & 28);
    float l1 = __shfl_sync(0xffffffffu, o[4][2], lane & 28);
    float inv0 = (l0 > 0.f) ? 1.f / l0 : 0.f;
    float inv1 = (l1 > 0.f) ? 1.f / l1 : 0.f;
    const float* xp0 = xn + (size_t)(b * SEQ + q0 + g) * D + h * DK;
    const float* xp1 = xp0 + 8 * D;
    float* op0 = sa + (size_t)(b * SEQ + q0 + g) * D + h * DK;
    float* op1 = op0 + 8 * D;
    #pragma unroll
    for (int nt = 0; nt < 4; nt++) {
        int col = nt * 8 + 2 * tig;
        float2 x0 = *(const float2*)(xp0 + col);
        float2 x1 = *(const float2*)(xp1 + col);
        *(float2*)(op0 + col) = make_float2(o[nt][0] * inv0 + x0.x, o[nt][1] * inv0 + x0.y);
        *(float2*)(op1 + col) = make_float2(o[nt][2] * inv1 + x1.x, o[nt][3] * inv1 + x1.y);
    }
}

// ---------------- launch ---------------------------------------------------------
extern "C" void kernel_launch(void* const* d_in, const int* in_sizes, int n_in,
                              void* d_out, int out_size) {
    const float* x    = (const float*)d_in[0];
    const int*   mask = (const int*)  d_in[1];
    const float* ln_w = (const float*)d_in[2];
    const float* ln_b = (const float*)d_in[3];
    const float* wq   = (const float*)d_in[4];
    const float* wk   = (const float*)d_in[5];
    const float* wv   = (const float*)d_in[6];
    const float* w1   = (const float*)d_in[7];
    const float* b1   = (const float*)d_in[8];
    const float* w2   = (const float*)d_in[9];
    const float* b2   = (const float*)d_in[10];
    float* out = (float*)d_out;

    float *xn, *sa;
    int *cntp, *idxp;
    __half *wh, *qh, *kh, *vh;
    cudaGetSymbolAddress((void**)&xn,   g_xn);
    cudaGetSymbolAddress((void**)&sa,   g_sa);
    cudaGetSymbolAddress((void**)&wh,   g_wh);
    cudaGetSymbolAddress((void**)&cntp, g_cnt);
    cudaGetSymbolAddress((void**)&idxp, g_idx);
    cudaGetSymbolAddress((void**)&qh,   g_qh);
    cudaGetSymbolAddress((void**)&kh,   g_kh);
    cudaGetSymbolAddress((void**)&vh,   g_vh);

    cudaFuncSetAttribute(qkv_kernel, cudaFuncAttributeMaxDynamicSharedMemorySize, GEMM_SMEM);
    cudaFuncSetAttribute(ffn_kernel, cudaFuncAttributeMaxDynamicSharedMemorySize, GEMM_SMEM);

    // 0) compact key indices + fp16-convert weights
    prep_kernel<<<96, 1024>>>(mask, idxp, cntp, wq, wk, wv, w1, w2, wh);
    // 1) fused LN + QKV (fp16, M=64, K=64 chunks)
    qkv_kernel<<<ROWS/MT, 256, GEMM_SMEM>>>(x, wh, wh + 16384, wh + 32768,
            ln_w, ln_b, xn, qh, kh, vh);
    // 2) attention (128-key tiles; writes sa = xn + attn)
    attn_f16_kernel<<<dim3(SEQ/128, BATCH*H), 256>>>(qh, kh, vh, idxp, cntp, xn, sa);
    // 3) fused LN + FFN (fp16, M=64, K=64 chunks)
    ffn_kernel<<<ROWS/MT, 256, GEMM_SMEM>>>(sa, wh + 49152, wh + 65536,
            ln_w, ln_b, b1, b2, out);
}